// round 6
// baseline (speedup 1.0000x reference)
#include <cuda_runtime.h>
#include <cstdint>

// CTC forward — one warp/batch, scaled-linear forward, PER-STATE scales with
// LOCAL-MAX renorm (no warp scan): c_s = max(L_s, L_{s-1}, L_{s-2}) - BIAS.
// All in-edge factors f = e^{c_src-c_dst} <= e^BIAS-ish; linear alphas only
// decay, so inflow telescopes to e^{L_src(t0)-c_dst}: no overflow.
// Inner loop: shfl + FMA only; p's prefetched to registers per 8-step macro.

#define CTC_B   256
#define CTC_T   512
#define CTC_C   128
#define CTC_L   64
#define BLANK   (CTC_C - 1)
#define WPC     2
#define MACRO   8
#define NMACRO  (CTC_T / MACRO)   // 64
#define EPS_F   1e-7f
#define FM      0xffffffffu
#define BIAS    35.0f
#define VFLOOR  1e-38f

__device__ __forceinline__ void cp_async16(void* smem_dst, const void* gmem_src) {
    unsigned saddr = (unsigned)__cvta_generic_to_shared(smem_dst);
    asm volatile("cp.async.cg.shared.global [%0], [%1], 16;\n"
                 :: "r"(saddr), "l"(gmem_src) : "memory");
}
#define CP_COMMIT() asm volatile("cp.async.commit_group;\n" ::: "memory")
#define CP_WAIT(n)  asm volatile("cp.async.wait_group %0;\n" :: "n"(n) : "memory")

template<bool TWO, bool E64>
__device__ __forceinline__ void ctc_warp(
    const float* __restrict__ yb,
    float (*ring)[MACRO][CTC_C],
    int lane, int l, int t_idx,
    int lab0, int lab1, float skm0, float skm1,
    float* __restrict__ outp)
{
    // prologue: macros 0,1 in flight
    #pragma unroll
    for (int mb = 0; mb < 2; ++mb) {
        #pragma unroll
        for (int r = 0; r < MACRO; ++r)
            cp_async16(&ring[mb][r][lane * 4],
                       yb + (size_t)(mb * MACRO + r) * CTC_C + lane * 4);
        CP_COMMIT();
    }
    CP_WAIT(1);
    __syncwarp();

    // state values / scales / edge factors
    float ve0 = (lane == 0) ? 1.0f : 0.0f;
    float vo0 = 0.f, ve1 = 0.f, vo1 = 0.f, ve64 = 0.f;
    float ce0 = 0.f, co0 = 0.f, ce1 = 0.f, co1 = 0.f, ce64 = 0.f;
    float fA0 = (lane == 0) ? 0.f : 1.f;   // odd[j-1] -> even[j]
    float fB0 = 1.f, fC0 = skm0;           // even[j]->odd[j], odd[j-1]->odd[j]
    float fA1 = 1.f, fB1 = 1.f, fC1 = skm1, fE = 1.f;

    // snapshot at t_idx
    float cv_e0 = 0.f, cv_o0 = 0.f, cv_e1 = 0.f, cv_o1 = 0.f, cv_e64 = 0.f;
    float cc_e0 = 0.f, cc_o0 = 0.f, cc_e1 = 0.f, cc_o1 = 0.f, cc_e64 = 0.f;

    const int mcap = t_idx >> 3;   // warp-uniform
    const int rcap = t_idx & 7;

    // p registers for the current macro
    float Pb[MACRO], P0[MACRO], P1[MACRO];
    {
        const float (*rows)[CTC_C] = ring[0];
        #pragma unroll
        for (int r = 0; r < MACRO; ++r) {
            Pb[r] = rows[r][BLANK] + EPS_F;
            P0[r] = rows[r][lab0] + EPS_F;
            if (TWO) P1[r] = rows[r][lab1] + EPS_F;
        }
    }

    #define CTC_STEP(r)                                                          \
    {                                                                            \
        float om0 = __shfl_up_sync(FM, vo0, 1);   /* lane0: own, f-masked */     \
        float ne0 = fmaf(fA0, om0, ve0) * Pb[r];                                 \
        float no0 = fmaf(fC0, om0, fmaf(fB0, ve0, vo0)) * P0[r];                 \
        if (TWO) {                                                               \
            float o0t = __shfl_sync(FM, vo0, 31);                                \
            float om1 = __shfl_up_sync(FM, vo1, 1);                              \
            if (lane == 0) om1 = o0t;                                            \
            float ne1 = fmaf(fA1, om1, ve1) * Pb[r];                             \
            float no1 = fmaf(fC1, om1, fmaf(fB1, ve1, vo1)) * P1[r];             \
            if (E64) {                                                           \
                float o1t = __shfl_sync(FM, vo1, 31);                            \
                ve64 = fmaf(fE, o1t, ve64) * Pb[r];                              \
            }                                                                    \
            ve1 = ne1; vo1 = no1;                                                \
        }                                                                        \
        ve0 = ne0; vo0 = no0;                                                    \
    }

    for (int m = 0; m < NMACRO; ++m) {
        // issue macro m+2
        if (m + 2 < NMACRO) {
            float* dst = &ring[(m + 2) % 3][0][0];
            const float* src = yb + (size_t)(m + 2) * MACRO * CTC_C;
            #pragma unroll
            for (int r = 0; r < MACRO; ++r)
                cp_async16(dst + r * CTC_C + lane * 4, src + r * CTC_C + lane * 4);
        }
        CP_COMMIT();

        // ---- 8 steps, pure shfl+FMA ----
        if (m == mcap) {
            #pragma unroll
            for (int r = 0; r < MACRO; ++r) {
                CTC_STEP(r);
                if (r == rcap) {
                    cv_e0 = ve0; cv_o0 = vo0; cv_e1 = ve1; cv_o1 = vo1; cv_e64 = ve64;
                    cc_e0 = ce0; cc_o0 = co0; cc_e1 = ce1; cc_o1 = co1; cc_e64 = ce64;
                }
            }
        } else {
            #pragma unroll
            for (int r = 0; r < MACRO; ++r)
                CTC_STEP(r);
        }

        // slot m+1 resident; prefetch next macro's p's (hidden under renorm MUFU)
        CP_WAIT(1);
        __syncwarp();
        if (m + 1 < NMACRO) {
            const float (*rows)[CTC_C] = ring[(m + 1) % 3];
            #pragma unroll
            for (int r = 0; r < MACRO; ++r) {
                Pb[r] = rows[r][BLANK] + EPS_F;
                P0[r] = rows[r][lab0] + EPS_F;
                if (TWO) P1[r] = rows[r][lab1] + EPS_F;
            }
        }

        // ---- local-max renorm ----
        {
            float Le0 = ce0 + __logf(fmaxf(ve0, VFLOOR));
            float Lo0 = co0 + __logf(fmaxf(vo0, VFLOOR));
            float Lom0 = __shfl_up_sync(FM, Lo0, 1);     // lane0: own (harmless)
            float t0 = fmaxf(Le0, Lom0);
            float nce0 = t0 - BIAS;
            float nco0 = fmaxf(t0, Lo0) - BIAS;
            float com0 = __shfl_up_sync(FM, nco0, 1);
            fA0 = (lane == 0) ? 0.f : __expf(com0 - nce0);
            fB0 = __expf(nce0 - nco0);
            fC0 = skm0 * fA0 * fB0;                      // lane0: skm0=0
            ve0 = __expf(Le0 - nce0);
            vo0 = __expf(Lo0 - nco0);
            ce0 = nce0; co0 = nco0;

            if (TWO) {
                float Le1 = ce1 + __logf(fmaxf(ve1, VFLOOR));
                float Lo1 = co1 + __logf(fmaxf(vo1, VFLOOR));
                float Lo0_31 = __shfl_sync(FM, Lo0, 31);
                float Lom1 = __shfl_up_sync(FM, Lo1, 1);
                if (lane == 0) Lom1 = Lo0_31;
                float t1 = fmaxf(Le1, Lom1);
                float nce1 = t1 - BIAS;
                float nco1 = fmaxf(t1, Lo1) - BIAS;
                float nco0_31 = __shfl_sync(FM, nco0, 31);
                float com1 = __shfl_up_sync(FM, nco1, 1);
                if (lane == 0) com1 = nco0_31;
                fA1 = __expf(com1 - nce1);
                fB1 = __expf(nce1 - nco1);
                fC1 = skm1 * fA1 * fB1;
                ve1 = __expf(Le1 - nce1);
                vo1 = __expf(Lo1 - nco1);
                ce1 = nce1; co1 = nco1;

                if (E64) {
                    float Le64 = ce64 + __logf(fmaxf(ve64, VFLOOR));
                    float Lo1_31 = __shfl_sync(FM, Lo1, 31);
                    float nco1_31 = __shfl_sync(FM, nco1, 31);
                    float nce64 = fmaxf(Le64, Lo1_31) - BIAS;
                    fE = __expf(nco1_31 - nce64);
                    ve64 = __expf(Le64 - nce64);
                    ce64 = nce64;
                }
            }
        }
    }
    #undef CTC_STEP

    // ---- extract loss = -logaddexp(L[2l], L[2l-1]) at t_idx ----
    float LLe0 = cc_e0 + __logf(fmaxf(cv_e0, 0.0f));
    float LLo0 = cc_o0 + __logf(fmaxf(cv_o0, 0.0f));
    float a_last, a_prev;
    if (E64) {
        a_last = cc_e64 + __logf(cv_e64);     // lane-invariant
    } else {
        float ev = LLe0;
        if (TWO) {
            float LLe1 = cc_e1 + __logf(cv_e1);
            ev = (l >= 32) ? LLe1 : LLe0;
        }
        a_last = __shfl_sync(FM, ev, l & 31);
    }
    {
        float ov = LLo0;
        if (TWO) {
            float LLo1 = cc_o1 + __logf(cv_o1);
            ov = ((l - 1) >= 32) ? LLo1 : LLo0;
        }
        a_prev = __shfl_sync(FM, ov, (l - 1) & 31);
    }
    if (lane == 0) {
        float mx = fmaxf(a_last, a_prev);
        *outp = -(mx + __logf(__expf(a_last - mx) + __expf(a_prev - mx)));
    }
}

__global__ __launch_bounds__(WPC * 32, 1)
void ctc_loss_kernel(const float* __restrict__ y_pred,
                     const int*   __restrict__ labels,
                     const int*   __restrict__ input_length,
                     const int*   __restrict__ label_length,
                     float*       __restrict__ out)
{
    __shared__ float rings[WPC][3][MACRO][CTC_C];   // 24 KB
    const int wid  = threadIdx.x >> 5;
    const int lane = threadIdx.x & 31;
    const int b = blockIdx.x * WPC + wid;
    const float* __restrict__ yb = y_pred + (size_t)b * CTC_T * CTC_C;

    const int l     = label_length[b];
    const int t_idx = input_length[b] - 1;

    const int lab0 = labels[b * CTC_L + lane];
    const int lab1 = labels[b * CTC_L + 32 + lane];
    const int lab0_31 = __shfl_sync(FM, lab0, 31);
    int lab0m = __shfl_up_sync(FM, lab0, 1);
    int lab1m = __shfl_up_sync(FM, lab1, 1);
    if (lane == 0) lab1m = lab0_31;
    const float skm0 = ((lane > 0) && (lab0 != lab0m)) ? 1.0f : 0.0f;
    const float skm1 = (lab1 != lab1m) ? 1.0f : 0.0f;

    if (l <= 31)
        ctc_warp<false, false>(yb, rings[wid], lane, l, t_idx, lab0, lab1, skm0, skm1, out + b);
    else if (l <= 63)
        ctc_warp<true, false>(yb, rings[wid], lane, l, t_idx, lab0, lab1, skm0, skm1, out + b);
    else
        ctc_warp<true, true>(yb, rings[wid], lane, l, t_idx, lab0, lab1, skm0, skm1, out + b);
}

extern "C" void kernel_launch(void* const* d_in, const int* in_sizes, int n_in,
                              void* d_out, int out_size) {
    const float* y_pred       = (const float*)d_in[0];
    const int*   labels       = (const int*)  d_in[1];
    const int*   input_length = (const int*)  d_in[2];
    const int*   label_length = (const int*)  d_in[3];
    float*       out          = (float*)d_out;

    ctc_loss_kernel<<<CTC_B / WPC, WPC * 32>>>(y_pred, labels, input_length, label_length, out);
}

// round 9
// speedup vs baseline: 1.1494x; 1.1494x over previous
#include <cuda_runtime.h>
#include <cstdint>

// CTC forward — one warp/batch, scaled-linear forward, BLOCKED layout:
// lane j holds alpha[4j..4j+3] (+ s=128 in lane 31). One shfl per step.
// Per-lane scale c_j, renormed every 8 steps to runmax(M)-BIAS (monotone ->
// cross-lane factor f <= 1). Inner loop: 1 shfl + ~12 FMA ops, no MUFU.

#define CTC_B   256
#define CTC_T   512
#define CTC_C   128
#define CTC_L   64
#define BLANK   (CTC_C - 1)
#define WPC     2
#define MACRO   8
#define NMACRO  (CTC_T / MACRO)   // 64
#define EPS_F   1e-7f
#define FM      0xffffffffu
#define BIAS    40.0f
#define VFLOOR  1e-38f

__device__ __forceinline__ void cp_async16(void* smem_dst, const void* gmem_src) {
    unsigned saddr = (unsigned)__cvta_generic_to_shared(smem_dst);
    asm volatile("cp.async.cg.shared.global [%0], [%1], 16;\n"
                 :: "r"(saddr), "l"(gmem_src) : "memory");
}
#define CP_COMMIT() asm volatile("cp.async.commit_group;\n" ::: "memory")
#define CP_WAIT(n)  asm volatile("cp.async.wait_group %0;\n" :: "n"(n) : "memory")

__global__ __launch_bounds__(WPC * 32, 1)
void ctc_loss_kernel(const float* __restrict__ y_pred,
                     const int*   __restrict__ labels,
                     const int*   __restrict__ input_length,
                     const int*   __restrict__ label_length,
                     float*       __restrict__ out)
{
    __shared__ float rings[WPC][3][MACRO][CTC_C];   // 24 KB
    const int wid  = threadIdx.x >> 5;
    const int lane = threadIdx.x & 31;
    const int b = blockIdx.x * WPC + wid;
    const float* __restrict__ yb = y_pred + (size_t)b * CTC_T * CTC_C;
    float (*ring)[MACRO][CTC_C] = rings[wid];

    const int l     = label_length[b];
    const int t_idx = input_length[b] - 1;

    // labels: lane j covers odd states 4j+1 (label 2j) and 4j+3 (label 2j+1)
    const int labA = labels[b * CTC_L + 2 * lane];
    const int labB = labels[b * CTC_L + 2 * lane + 1];
    const int labBm = __shfl_up_sync(FM, labB, 1);          // lab[2j-1]
    const float sk1 = ((lane > 0) && (labA != labBm)) ? 1.0f : 0.0f;  // s=4j+1
    const float sk3 = (labB != labA) ? 1.0f : 0.0f;                   // s=4j+3

    // prologue: macros 0,1 in flight
    #pragma unroll
    for (int mb = 0; mb < 2; ++mb) {
        #pragma unroll
        for (int r = 0; r < MACRO; ++r)
            cp_async16(&ring[mb][r][lane * 4],
                       yb + (size_t)(mb * MACRO + r) * CTC_C + lane * 4);
        CP_COMMIT();
    }
    CP_WAIT(1);
    __syncwarp();

    // state (values in lane scale c), cross-lane factor f
    float a0 = (lane == 0) ? 1.0f : 0.0f;   // seed: generic step at t=0 gives alpha0
    float a1 = 0.f, a2 = 0.f, a3 = 0.f, e64 = 0.f;
    float c = 0.f;
    float f  = (lane == 0) ? 0.f : 1.f;
    float fs1 = sk1 * f;

    // snapshot at t_idx
    float cv0 = 0.f, cv1 = 0.f, cv2 = 0.f, cv3 = 0.f, cve = 0.f, cvc = 0.f;

    const int mcap = t_idx >> 3;    // warp-uniform
    const int rcap = t_idx & 7;

    float Pb[MACRO], P0[MACRO], P1[MACRO];
    {
        const float (*rows)[CTC_C] = ring[0];
        #pragma unroll
        for (int r = 0; r < MACRO; ++r) {
            Pb[r] = rows[r][BLANK] + EPS_F;
            P0[r] = rows[r][labA] + EPS_F;
            P1[r] = rows[r][labB] + EPS_F;
        }
    }

    #define CTC_STEP(r)                                                   \
    {                                                                     \
        float x = __shfl_up_sync(FM, a3, 1);   /* alpha[4j-1]; lane0 f=0 */\
        float ne = (e64 + a3) * Pb[r];         /* s=128 (lane31 only) */  \
        float s23 = a3 + a2;                                              \
        float na3 = fmaf(sk3, a1, s23) * P1[r];                           \
        float na2 = (a2 + a1) * Pb[r];                                    \
        float s01 = a1 + a0;                                              \
        float na1 = fmaf(fs1, x, s01) * P0[r];                            \
        float na0 = fmaf(f, x, a0) * Pb[r];                               \
        a0 = na0; a1 = na1; a2 = na2; a3 = na3; e64 = ne;                 \
    }

    for (int m = 0; m < NMACRO; ++m) {
        // issue macro m+2
        if (m + 2 < NMACRO) {
            float* dst = &ring[(m + 2) % 3][0][0];
            const float* src = yb + (size_t)(m + 2) * MACRO * CTC_C;
            #pragma unroll
            for (int r = 0; r < MACRO; ++r)
                cp_async16(dst + r * CTC_C + lane * 4, src + r * CTC_C + lane * 4);
        }
        CP_COMMIT();

        if (m == mcap) {
            #pragma unroll
            for (int r = 0; r < MACRO; ++r) {
                CTC_STEP(r);
                if (r == rcap) {
                    cv0 = a0; cv1 = a1; cv2 = a2; cv3 = a3; cve = e64; cvc = c;
                }
            }
        } else {
            #pragma unroll
            for (int r = 0; r < MACRO; ++r)
                CTC_STEP(r);
        }

        // next macro resident; prefetch its p's (hides under renorm MUFU chain)
        CP_WAIT(1);
        __syncwarp();
        if (m + 1 < NMACRO) {
            const float (*rows)[CTC_C] = ring[(m + 1) % 3];
            #pragma unroll
            for (int r = 0; r < MACRO; ++r) {
                Pb[r] = rows[r][BLANK] + EPS_F;
                P0[r] = rows[r][labA] + EPS_F;
                P1[r] = rows[r][labB] + EPS_F;
            }
        }

        // ---- renorm: per-lane scale = runmax over lanes of local max, - BIAS ----
        {
            float L0 = c + __logf(fmaxf(a0, VFLOOR));
            float L1 = c + __logf(fmaxf(a1, VFLOOR));
            float L2 = c + __logf(fmaxf(a2, VFLOOR));
            float L3 = c + __logf(fmaxf(a3, VFLOOR));
            float Le = c + __logf(fmaxf(e64, VFLOOR));
            float M = fmaxf(fmaxf(L0, L1), fmaxf(L2, L3));
            M = fmaxf(M, (lane == 31) ? Le : -1e30f);   // e64 valid only in lane 31

            float R = M;
            #pragma unroll
            for (int d = 1; d < 32; d <<= 1)
                R = fmaxf(R, __shfl_up_sync(FM, R, d));  // inclusive runmax (monotone)

            float nc = R - BIAS;
            float ncm = __shfl_up_sync(FM, nc, 1);
            f = (lane == 0) ? 0.f : __expf(ncm - nc);    // <= 1 by monotonicity
            fs1 = sk1 * f;
            a0 = __expf(L0 - nc);
            a1 = __expf(L1 - nc);
            a2 = __expf(L2 - nc);
            a3 = __expf(L3 - nc);
            e64 = __expf(Le - nc);
            c = nc;
        }
    }
    #undef CTC_STEP

    // ---- extract loss = -logaddexp(L[2l], L[2l-1]) at t_idx ----
    float a_last;
    if (l == 64) {                                       // warp-uniform
        float v  = __shfl_sync(FM, cve, 31);
        float cc = __shfl_sync(FM, cvc, 31);
        a_last = cc + __logf(fmaxf(v, VFLOOR));
    } else {
        const int sE = 2 * l, ln = sE >> 2, ix = sE & 3; // ix in {0,2}
        float g0 = __shfl_sync(FM, cv0, ln);
        float g2 = __shfl_sync(FM, cv2, ln);
        float cc = __shfl_sync(FM, cvc, ln);
        a_last = cc + __logf(fmaxf(ix ? g2 : g0, VFLOOR));
    }
    {
        const int sP = 2 * l - 1, ln = sP >> 2, ix = sP & 3;  // ix in {1,3}
        float g1 = __shfl_sync(FM, cv1, ln);
        float g3 = __shfl_sync(FM, cv3, ln);
        float cc = __shfl_sync(FM, cvc, ln);
        float a_prev = cc + __logf(fmaxf((ix == 3) ? g3 : g1, VFLOOR));
        if (lane == 0) {
            float mx = fmaxf(a_last, a_prev);
            out[b] = -(mx + __logf(__expf(a_last - mx) + __expf(a_prev - mx)));
        }
    }
}

extern "C" void kernel_launch(void* const* d_in, const int* in_sizes, int n_in,
                              void* d_out, int out_size) {
    const float* y_pred       = (const float*)d_in[0];
    const int*   labels       = (const int*)  d_in[1];
    const int*   input_length = (const int*)  d_in[2];
    const int*   label_length = (const int*)  d_in[3];
    float*       out          = (float*)d_out;

    ctc_loss_kernel<<<CTC_B / WPC, WPC * 32>>>(y_pred, labels, input_length, label_length, out);
}

// round 15
// speedup vs baseline: 1.2173x; 1.0591x over previous
#include <cuda_runtime.h>
#include <cstdint>

// CTC forward — one warp/batch, scaled-linear forward, BLOCKED layout:
// lane j holds alpha[4j..4j+3] (+ s=128 in lane 31). One shfl per step.
// Renorm every 8 steps (R6's proven cadence/BIAS): monotone runmax scan
// (f <= 1, values <= e^BIAS) + CHEAP two-stage rescale a*(s2)*(s2) with
// s2 = exp((c-nc)/2): exact (no clamp), overflow-free (s2 <= e^72,
// intermediate <= e^{BIAS/2}). 1 log + 2 exp per renorm vs R6's 5+7.

#define CTC_B   256
#define CTC_T   512
#define CTC_C   128
#define CTC_L   64
#define BLANK   (CTC_C - 1)
#define WPC     2
#define MACRO   8
#define NMACRO  (CTC_T / MACRO)   // 64
#define EPS_F   1e-7f
#define FM      0xffffffffu
#define BIAS    40.0f
#define MFLOOR  1e-37f

__device__ __forceinline__ void cp_async16(void* smem_dst, const void* gmem_src) {
    unsigned saddr = (unsigned)__cvta_generic_to_shared(smem_dst);
    asm volatile("cp.async.cg.shared.global [%0], [%1], 16;\n"
                 :: "r"(saddr), "l"(gmem_src) : "memory");
}
#define CP_COMMIT() asm volatile("cp.async.commit_group;\n" ::: "memory")
#define CP_WAIT(n)  asm volatile("cp.async.wait_group %0;\n" :: "n"(n) : "memory")

__global__ __launch_bounds__(WPC * 32, 1)
void ctc_loss_kernel(const float* __restrict__ y_pred,
                     const int*   __restrict__ labels,
                     const int*   __restrict__ input_length,
                     const int*   __restrict__ label_length,
                     float*       __restrict__ out)
{
    __shared__ float rings[WPC][3][MACRO][CTC_C];   // 24 KB
    const int wid  = threadIdx.x >> 5;
    const int lane = threadIdx.x & 31;
    const int b = blockIdx.x * WPC + wid;
    const float* __restrict__ yb = y_pred + (size_t)b * CTC_T * CTC_C;
    float (*ring)[MACRO][CTC_C] = rings[wid];

    const int l     = label_length[b];
    const int t_idx = input_length[b] - 1;

    // labels: lane j covers odd states 4j+1 (label 2j) and 4j+3 (label 2j+1)
    const int labA = labels[b * CTC_L + 2 * lane];
    const int labB = labels[b * CTC_L + 2 * lane + 1];
    const int labBm = __shfl_up_sync(FM, labB, 1);          // lab[2j-1]
    const float sk1 = ((lane > 0) && (labA != labBm)) ? 1.0f : 0.0f;  // s=4j+1
    const float sk3 = (labB != labA) ? 1.0f : 0.0f;                   // s=4j+3

    // prologue: macros 0,1 in flight
    #pragma unroll
    for (int mb = 0; mb < 2; ++mb) {
        #pragma unroll
        for (int r = 0; r < MACRO; ++r)
            cp_async16(&ring[mb][r][lane * 4],
                       yb + (size_t)(mb * MACRO + r) * CTC_C + lane * 4);
        CP_COMMIT();
    }
    CP_WAIT(1);
    __syncwarp();

    // state (values in lane scale c), cross-lane factor f
    float a0 = (lane == 0) ? 1.0f : 0.0f;   // seed: generic step at t=0 gives alpha0
    float a1 = 0.f, a2 = 0.f, a3 = 0.f, e64 = 0.f;
    float c = 0.f;
    float f  = (lane == 0) ? 0.f : 1.f;
    float fs1 = sk1 * f;

    // snapshot at t_idx
    float cv0 = 0.f, cv1 = 0.f, cv2 = 0.f, cv3 = 0.f, cve = 0.f, cvc = 0.f;

    const int mcap = t_idx >> 3;    // warp-uniform
    const int rcap = t_idx & 7;

    float Pb[MACRO], P0[MACRO], P1[MACRO];
    {
        const float (*rows)[CTC_C] = ring[0];
        #pragma unroll
        for (int r = 0; r < MACRO; ++r) {
            Pb[r] = rows[r][BLANK] + EPS_F;
            P0[r] = rows[r][labA] + EPS_F;
            P1[r] = rows[r][labB] + EPS_F;
        }
    }

    #define CTC_STEP(r)                                                   \
    {                                                                     \
        float x = __shfl_up_sync(FM, a3, 1);   /* alpha[4j-1]; lane0 f=0 */\
        float ne = (e64 + a3) * Pb[r];         /* s=128 (lane31 only) */  \
        float s23 = a3 + a2;                                              \
        float na3 = fmaf(sk3, a1, s23) * P1[r];                           \
        float na2 = (a2 + a1) * Pb[r];                                    \
        float s01 = a1 + a0;                                              \
        float na1 = fmaf(fs1, x, s01) * P0[r];                            \
        float na0 = fmaf(f, x, a0) * Pb[r];                               \
        a0 = na0; a1 = na1; a2 = na2; a3 = na3; e64 = ne;                 \
    }

    for (int m = 0; m < NMACRO; ++m) {
        // issue macro m+2
        if (m + 2 < NMACRO) {
            float* dst = &ring[(m + 2) % 3][0][0];
            const float* src = yb + (size_t)(m + 2) * MACRO * CTC_C;
            #pragma unroll
            for (int r = 0; r < MACRO; ++r)
                cp_async16(dst + r * CTC_C + lane * 4, src + r * CTC_C + lane * 4);
        }
        CP_COMMIT();

        if (m == mcap) {
            #pragma unroll
            for (int r = 0; r < MACRO; ++r) {
                CTC_STEP(r);
                if (r == rcap) {
                    cv0 = a0; cv1 = a1; cv2 = a2; cv3 = a3; cve = e64; cvc = c;
                }
            }
        } else {
            #pragma unroll
            for (int r = 0; r < MACRO; ++r)
                CTC_STEP(r);
        }

        // next macro resident; prefetch its p's (hides under renorm chain)
        CP_WAIT(1);
        __syncwarp();
        if (m + 1 < NMACRO) {
            const float (*rows)[CTC_C] = ring[(m + 1) % 3];
            #pragma unroll
            for (int r = 0; r < MACRO; ++r) {
                Pb[r] = rows[r][BLANK] + EPS_F;
                P0[r] = rows[r][labA] + EPS_F;
                P1[r] = rows[r][labB] + EPS_F;
            }
        }

        // ---- renorm every macro (8 steps), R6 envelope, cheap rescale ----
        {
            float maxa = fmaxf(fmaxf(a0, a1), fmaxf(a2, a3));
            maxa = fmaxf(maxa, (lane == 31) ? e64 : 0.0f);   // e64 junk elsewhere
            float M = c + __logf(fmaxf(maxa, MFLOOR));

            float R = M;                                     // inclusive runmax
            #pragma unroll
            for (int d = 1; d < 32; d <<= 1)
                R = fmaxf(R, __shfl_up_sync(FM, R, d));      // monotone in lane

            float nc = R - BIAS;
            float ncm = __shfl_up_sync(FM, nc, 1);
            f = (lane == 0) ? 0.f : __expf(fminf(ncm - nc, 0.0f));  // <= 1
            fs1 = sk1 * f;
            // two-stage rescale: exact, overflow-free (no clamp on the product)
            float s2 = __expf(0.5f * (c - nc));              // <= e^72
            a0 = (a0 * s2) * s2;
            a1 = (a1 * s2) * s2;
            a2 = (a2 * s2) * s2;
            a3 = (a3 * s2) * s2;
            e64 = (e64 * s2) * s2;
            c = nc;
        }
    }
    #undef CTC_STEP

    // ---- extract loss = -logaddexp(L[2l], L[2l-1]) at t_idx ----
    float a_last;
    if (l == 64) {                                       // warp-uniform
        float v  = __shfl_sync(FM, cve, 31);
        float cc = __shfl_sync(FM, cvc, 31);
        a_last = cc + __logf(fmaxf(v, MFLOOR));
    } else {
        const int sE = 2 * l, ln = sE >> 2, ix = sE & 3; // ix in {0,2}
        float g0 = __shfl_sync(FM, cv0, ln);
        float g2 = __shfl_sync(FM, cv2, ln);
        float cc = __shfl_sync(FM, cvc, ln);
        a_last = cc + __logf(fmaxf(ix ? g2 : g0, MFLOOR));
    }
    {
        const int sP = 2 * l - 1, ln = sP >> 2, ix = sP & 3;  // ix in {1,3}
        float g1 = __shfl_sync(FM, cv1, ln);
        float g3 = __shfl_sync(FM, cv3, ln);
        float cc = __shfl_sync(FM, cvc, ln);
        float a_prev = cc + __logf(fmaxf((ix == 3) ? g3 : g1, MFLOOR));
        if (lane == 0) {
            float mx = fmaxf(a_last, a_prev);
            out[b] = -(mx + __logf(__expf(a_last - mx) + __expf(a_prev - mx)));
        }
    }
}

extern "C" void kernel_launch(void* const* d_in, const int* in_sizes, int n_in,
                              void* d_out, int out_size) {
    const float* y_pred       = (const float*)d_in[0];
    const int*   labels       = (const int*)  d_in[1];
    const int*   input_length = (const int*)  d_in[2];
    const int*   label_length = (const int*)  d_in[3];
    float*       out          = (float*)d_out;

    ctc_loss_kernel<<<CTC_B / WPC, WPC * 32>>>(y_pred, labels, input_length, label_length, out);
}